// round 8
// baseline (speedup 1.0000x reference)
#include <cuda_runtime.h>

// RSA_layer: output = c[-1] only  =>  softmax needed only for row i=1023.
//   s[j,u] = (fs @ w_hi)[j,u] + q[j]*w_dot[u],   q[j] = x . fs[j]
//   out[u] = sum_j fs[j,u]*exp(s[j,u]) / sum_j exp(s[j,u])
// Logits O(1) => exp without max-subtraction (validated rel_err ~2e-7).
// fs[j,v] = state[v*1024 + j + 1] for j < 1023;  fs[1023,v] = x[v]
//
// R8: u-pair x v-quarter decomposition. Thread (p, s) owns u in {2p,2p+1},
// v in [32s, 32s+32), all 8 j:
//  - w loads are LDG.64 float2 -> warp-LDG instrs/SM 512 -> 256
//  - fs LDS.128 shared across the u-pair -> LDS requests/SM 1024 -> 512
//  - FFMA2 per SMSP unchanged (invariant); 4-way combine via smem.

#define UNITS 128
#define WIN   1024
#define NBLK  128
#define TPB   256
#define JB    8           // j-rows per block
#define VS    32          // v-range per slice
#define NSLC  4

typedef unsigned long long u64;

__device__ float2 g_zc[NBLK * UNITS];
__device__ unsigned int g_cnt = 0;

__device__ __forceinline__ u64 pack2(float lo, float hi) {
    u64 r;
    asm("mov.b64 %0, {%1, %2};" : "=l"(r) : "f"(lo), "f"(hi));
    return r;
}
__device__ __forceinline__ void unpack2(u64 p, float& lo, float& hi) {
    asm("mov.b64 {%0, %1}, %2;" : "=f"(lo), "=f"(hi) : "l"(p));
}
__device__ __forceinline__ u64 ffma2(u64 a, u64 b, u64 c) {
    u64 d;
    asm("fma.rn.f32x2 %0, %1, %2, %3;" : "=l"(d) : "l"(a), "l"(b), "l"(c));
    return d;
}

__global__ void __launch_bounds__(TPB)
rsa_fused(const float* __restrict__ x,
          const float* __restrict__ state,
          const float* __restrict__ w,
          float* __restrict__ out)
{
    __shared__ __align__(16) float fs_sh[UNITS][JB];       // [v][j] (4KB)
    __shared__ float x_sh[UNITS];
    __shared__ float q_sh[JB];
    __shared__ __align__(16) float comb[NSLC - 1][UNITS][JB];  // 12KB
    __shared__ unsigned int s_ticket;

    const int t  = threadIdx.x;
    const int p  = t & 63;                // u-pair index: u = 2p, 2p+1
    const int sl = t >> 6;                // v-slice 0..3: v in [32*sl, 32*sl+32)
    const int j0 = blockIdx.x * JB;

    if (t < UNITS) x_sh[t] = x[t];

    // fs tile: 128v x 8j = 1024 floats, 4 per thread.
    #pragma unroll
    for (int k = 0; k < 4; k++) {
        int i = t + k * TPB;
        int v = i >> 3, j = i & (JB - 1);
        int jj = j0 + j;
        fs_sh[v][j] = (jj < WIN - 1) ? state[v * WIN + jj + 1] : x[v];
    }

    // w_hi[v][2p..2p+1] for this slice's 32 v: 32 independent LDG.64
    // (lanes cover 256B contiguous -> 2 lines per warp-LDG).
    const float2* __restrict__ wu =
        (const float2*)(w + sl * VS * UNITS + 2 * p);
    float2 wr[VS];
    #pragma unroll
    for (int i = 0; i < VS; i++) wr[i] = wu[i * (UNITS / 2)];

    __syncthreads();   // fs_sh / x_sh ready

    // q[j] = fs[j].x : 8 warps, warp jw owns one j.
    {
        const int warp = t >> 5, lane = t & 31;
        float pq = fs_sh[lane][warp]      * x_sh[lane]
                 + fs_sh[lane + 32][warp] * x_sh[lane + 32]
                 + fs_sh[lane + 64][warp] * x_sh[lane + 64]
                 + fs_sh[lane + 96][warp] * x_sh[lane + 96];
        #pragma unroll
        for (int o = 16; o; o >>= 1) pq += __shfl_xor_sync(0xffffffffu, pq, o);
        if (lane == 0) q_sh[warp] = pq;
    }

    // Partial GEMM: per v {2x LDS.128 (shared by both u) + 2 packs + 8 FFMA2}.
    u64 a01 = 0, a23 = 0, a45 = 0, a67 = 0;   // u = 2p
    u64 b01 = 0, b23 = 0, b45 = 0, b67 = 0;   // u = 2p+1
    #pragma unroll
    for (int i = 0; i < VS; i++) {
        u64 wa = pack2(wr[i].x, wr[i].x);
        u64 wb = pack2(wr[i].y, wr[i].y);
        const ulonglong2* fp = (const ulonglong2*)fs_sh[sl * VS + i];
        ulonglong2 f = fp[0];                 // j0..3 broadcast
        ulonglong2 g = fp[1];                 // j4..7 broadcast
        a01 = ffma2(f.x, wa, a01);  b01 = ffma2(f.x, wb, b01);
        a23 = ffma2(f.y, wa, a23);  b23 = ffma2(f.y, wb, b23);
        a45 = ffma2(g.x, wa, a45);  b45 = ffma2(g.x, wb, b45);
        a67 = ffma2(g.y, wa, a67);  b67 = ffma2(g.y, wb, b67);
    }

    float sa[JB], sb[JB];
    unpack2(a01, sa[0], sa[1]); unpack2(a23, sa[2], sa[3]);
    unpack2(a45, sa[4], sa[5]); unpack2(a67, sa[6], sa[7]);
    unpack2(b01, sb[0], sb[1]); unpack2(b23, sb[2], sb[3]);
    unpack2(b45, sb[4], sb[5]); unpack2(b67, sb[6], sb[7]);

    // Slices 1..3 publish partials (4x STS.128 each).
    if (sl > 0) {
        *(float4*)&comb[sl - 1][2 * p][0]     = make_float4(sa[0], sa[1], sa[2], sa[3]);
        *(float4*)&comb[sl - 1][2 * p][4]     = make_float4(sa[4], sa[5], sa[6], sa[7]);
        *(float4*)&comb[sl - 1][2 * p + 1][0] = make_float4(sb[0], sb[1], sb[2], sb[3]);
        *(float4*)&comb[sl - 1][2 * p + 1][4] = make_float4(sb[4], sb[5], sb[6], sb[7]);
    }
    __syncthreads();   // also publishes q_sh

    // Slice 0 combines + softmax partials for its u-pair.
    if (sl == 0) {
        const float2 wd2 = *(const float2*)(w + 2 * UNITS * UNITS + 2 * p);
        float za = 0.f, ca = 0.f, zb = 0.f, cb = 0.f;
        #pragma unroll
        for (int j = 0; j < JB; j++) {
            float va = sa[j] + comb[0][2 * p][j] + comb[1][2 * p][j] + comb[2][2 * p][j];
            float vb = sb[j] + comb[0][2 * p + 1][j] + comb[1][2 * p + 1][j] + comb[2][2 * p + 1][j];
            float ea = __expf(fmaf(q_sh[j], wd2.x, va));
            float eb = __expf(fmaf(q_sh[j], wd2.y, vb));
            za += ea;  ca = fmaf(ea, fs_sh[2 * p][j],     ca);
            zb += eb;  cb = fmaf(eb, fs_sh[2 * p + 1][j], cb);
        }
        // (z,c,z,c) for consecutive u -> one STG.128
        *(float4*)&g_zc[blockIdx.x * UNITS + 2 * p] = make_float4(za, ca, zb, cb);
    }

    // Ticket: last-arriving block finalizes.
    __threadfence();
    __syncthreads();
    if (t == 0) s_ticket = atomicAdd(&g_cnt, 1u);
    __syncthreads();

    if (s_ticket == NBLK - 1) {
        __threadfence();   // acquire side
        if (t < UNITS) {
            float Z = 0.0f, C = 0.0f;
            #pragma unroll 32
            for (int b = 0; b < NBLK; b++) {          // coalesced LDG.64, L2-resident
                float2 pz = g_zc[b * UNITS + t];
                Z += pz.x;
                C += pz.y;
            }
            out[t] = C / Z;
        }
        if (t == 0) g_cnt = 0;                        // reset for next graph replay
    }
}

extern "C" void kernel_launch(void* const* d_in, const int* in_sizes, int n_in,
                              void* d_out, int out_size)
{
    const float* x     = (const float*)d_in[0];   // input_tensor (1,128)
    const float* state = (const float*)d_in[1];   // state (128,1024)
    const float* w     = (const float*)d_in[2];   // w (257,128)
    // d_in[3] = b — cancels inside the softmax, unused.

    rsa_fused<<<NBLK, TPB>>>(x, state, w, (float*)d_out);
}

// round 9
// speedup vs baseline: 1.0025x; 1.0025x over previous
#include <cuda_runtime.h>

// RSA_layer: output = c[-1] only  =>  softmax needed only for row i=1023.
//   s[j,u] = (fs @ w_hi)[j,u] + q[j]*w_dot[u],   q[j] = x . fs[j]
//   out[u] = sum_j fs[j,u]*exp(s[j,u]) / sum_j exp(s[j,u])
// Logits O(1) => exp without max-subtraction (validated rel_err ~2e-7).
// fs[j,v] = state[v*1024 + j + 1] for j < 1023;  fs[1023,v] = x[v]
//
// R9: R7 base (v-half split, regs~40, best bench) + two-level 256-thread
// finalize: each thread sums 64 partials (half depth), halves combined in
// smem -> ~2 fewer exposed L2 latency rounds on the serial tail.

#define UNITS 128
#define WIN   1024
#define NBLK  128
#define TPB   256
#define JB    8           // j-rows per block (all 8 per thread)
#define VH    64          // v-range per half

typedef unsigned long long u64;

__device__ float2 g_zc[NBLK * UNITS];
__device__ unsigned int g_cnt = 0;

__device__ __forceinline__ u64 pack2(float lo, float hi) {
    u64 r;
    asm("mov.b64 %0, {%1, %2};" : "=l"(r) : "f"(lo), "f"(hi));
    return r;
}
__device__ __forceinline__ void unpack2(u64 p, float& lo, float& hi) {
    asm("mov.b64 {%0, %1}, %2;" : "=f"(lo), "=f"(hi) : "l"(p));
}
__device__ __forceinline__ u64 ffma2(u64 a, u64 b, u64 c) {
    u64 d;
    asm("fma.rn.f32x2 %0, %1, %2, %3;" : "=l"(d) : "l"(a), "l"(b), "l"(c));
    return d;
}

__global__ void __launch_bounds__(TPB)
rsa_fused(const float* __restrict__ x,
          const float* __restrict__ state,
          const float* __restrict__ w,
          float* __restrict__ out)
{
    __shared__ __align__(16) float fs_sh[UNITS][JB];   // [v][j], j contiguous (4KB)
    __shared__ float x_sh[UNITS];
    __shared__ float q_sh[JB];
    __shared__ __align__(16) float comb[UNITS][JB];    // half-1 GEMM partials (4KB)
    __shared__ unsigned int s_ticket;

    const int t  = threadIdx.x;
    const int u  = t & (UNITS - 1);       // output column
    const int h  = t >> 7;                // v-half: 0 -> v[0,64), 1 -> v[64,128)
    const int j0 = blockIdx.x * JB;

    if (t < UNITS) x_sh[t] = x[t];

    // fs tile: 128v x 8j = 1024 floats, 4 per thread.
    #pragma unroll
    for (int k = 0; k < 4; k++) {
        int i = t + k * TPB;
        int v = i >> 3, j = i & (JB - 1);
        int jj = j0 + j;
        fs_sh[v][j] = (jj < WIN - 1) ? state[v * WIN + jj + 1] : x[v];
    }

    // This thread's 64-v slice of w_hi column u: 64 independent LDGs.
    const float* __restrict__ wu = w + h * VH * UNITS + u;  // w_hi[h*64+i][u]
    const float wd = w[2 * UNITS * UNITS + u];              // w_dot[u]
    float wr[VH];
    #pragma unroll
    for (int i = 0; i < VH; i++) wr[i] = wu[i * UNITS];

    __syncthreads();   // fs_sh / x_sh ready

    // q[j] = fs[j].x : 8 warps, warp jw owns one j (overlaps GEMM issue).
    {
        const int warp = t >> 5, lane = t & 31;
        float p = fs_sh[lane][warp]      * x_sh[lane]
                + fs_sh[lane + 32][warp] * x_sh[lane + 32]
                + fs_sh[lane + 64][warp] * x_sh[lane + 64]
                + fs_sh[lane + 96][warp] * x_sh[lane + 96];
        #pragma unroll
        for (int o = 16; o; o >>= 1) p += __shfl_xor_sync(0xffffffffu, p, o);
        if (lane == 0) q_sh[warp] = p;
    }

    // Partial GEMM over this half's v: {2x LDS.128 + 4x FFMA2} per v.
    u64 s01 = 0, s23 = 0, s45 = 0, s67 = 0;
    #pragma unroll
    for (int i = 0; i < VH; i++) {
        u64 w2 = pack2(wr[i], wr[i]);                 // alu-pipe
        const ulonglong2* fp = (const ulonglong2*)fs_sh[h * VH + i];
        ulonglong2 f = fp[0];                         // j0..3 broadcast
        s01 = ffma2(f.x, w2, s01);
        s23 = ffma2(f.y, w2, s23);
        ulonglong2 g = fp[1];                         // j4..7 broadcast
        s45 = ffma2(g.x, w2, s45);
        s67 = ffma2(g.y, w2, s67);
    }

    float sp[JB];
    unpack2(s01, sp[0], sp[1]);
    unpack2(s23, sp[2], sp[3]);
    unpack2(s45, sp[4], sp[5]);
    unpack2(s67, sp[6], sp[7]);

    // Half-1 publishes its partials (2x STS.128).
    if (h == 1) {
        *(float4*)&comb[u][0] = make_float4(sp[0], sp[1], sp[2], sp[3]);
        *(float4*)&comb[u][4] = make_float4(sp[4], sp[5], sp[6], sp[7]);
    }
    __syncthreads();   // also publishes q_sh

    // Half-0 combines, applies q*wd, computes softmax partials.
    if (h == 0) {
        float z = 0.0f, c = 0.0f;
        #pragma unroll
        for (int j = 0; j < JB; j++) {
            float sj = sp[j] + comb[u][j];
            float e  = __expf(fmaf(q_sh[j], wd, sj));
            z += e;
            c = fmaf(e, fs_sh[u][j], c);              // fs[j][u]
        }
        g_zc[blockIdx.x * UNITS + u] = make_float2(z, c);
    }

    // Ticket: last-arriving block finalizes.
    __threadfence();
    __syncthreads();
    if (t == 0) s_ticket = atomicAdd(&g_cnt, 1u);
    __syncthreads();

    if (s_ticket == NBLK - 1) {                       // uniform branch (smem bcast)
        __threadfence();   // acquire side
        // Two-level finalize: thread (u, h) sums its 64-block half.
        float Z = 0.0f, C = 0.0f;
        const int b0 = h * (NBLK / 2);
        #pragma unroll 16
        for (int b = b0; b < b0 + NBLK / 2; b++) {    // coalesced LDG.64, L2-resident
            float2 p = g_zc[b * UNITS + u];
            Z += p.x;
            C += p.y;
        }
        float2* c2 = (float2*)comb;                   // reuse smem
        if (h == 1) c2[u] = make_float2(Z, C);
        __syncthreads();
        if (h == 0) {
            float2 p = c2[u];
            out[u] = (C + p.y) / (Z + p.x);
        }
        if (t == 0) g_cnt = 0;                        // reset for next graph replay
    }
}

extern "C" void kernel_launch(void* const* d_in, const int* in_sizes, int n_in,
                              void* d_out, int out_size)
{
    const float* x     = (const float*)d_in[0];   // input_tensor (1,128)
    const float* state = (const float*)d_in[1];   // state (128,1024)
    const float* w     = (const float*)d_in[2];   // w (257,128)
    // d_in[3] = b — cancels inside the softmax, unused.

    rsa_fused<<<NBLK, TPB>>>(x, state, w, (float*)d_out);
}

// round 10
// speedup vs baseline: 1.0226x; 1.0201x over previous
#include <cuda_runtime.h>

// RSA_layer: output = c[-1] only  =>  softmax needed only for row i=1023.
//   s[j,u] = (fs @ w_hi)[j,u] + q[j]*w_dot[u],   q[j] = x . fs[j]
//   out[u] = sum_j fs[j,u]*exp(s[j,u]) / sum_j exp(s[j,u])
// Logits O(1) => exp without max-subtraction (validated rel_err ~2e-7).
// fs[j,v] = state[v*1024 + j + 1] for j < 1023;  fs[1023,v] = x[v]
//
// R10: R7 body (v-half split, best measured) + REDG-accumulated finalize:
// blocks red.add their (z,c) partials into g_acc; last-ticket block does ONE
// L2 read round + divide + reset (replaces the 64-deep serial read chain).

#define UNITS 128
#define WIN   1024
#define NBLK  128
#define TPB   256
#define JB    8           // j-rows per block
#define VH    64          // v-range per half

typedef unsigned long long u64;

__device__ float2 g_acc[UNITS];        // zero at module load; reset each replay
__device__ unsigned int g_cnt = 0;

__device__ __forceinline__ u64 pack2(float lo, float hi) {
    u64 r;
    asm("mov.b64 %0, {%1, %2};" : "=l"(r) : "f"(lo), "f"(hi));
    return r;
}
__device__ __forceinline__ void unpack2(u64 p, float& lo, float& hi) {
    asm("mov.b64 {%0, %1}, %2;" : "=f"(lo), "=f"(hi) : "l"(p));
}
__device__ __forceinline__ u64 ffma2(u64 a, u64 b, u64 c) {
    u64 d;
    asm("fma.rn.f32x2 %0, %1, %2, %3;" : "=l"(d) : "l"(a), "l"(b), "l"(c));
    return d;
}

__global__ void __launch_bounds__(TPB)
rsa_fused(const float* __restrict__ x,
          const float* __restrict__ state,
          const float* __restrict__ w,
          float* __restrict__ out)
{
    __shared__ __align__(16) float fs_sh[UNITS][JB];   // [v][j], j contiguous (4KB)
    __shared__ float x_sh[UNITS];
    __shared__ float q_sh[JB];
    __shared__ __align__(16) float comb[UNITS][JB];    // half-1 GEMM partials (4KB)
    __shared__ unsigned int s_ticket;

    const int t  = threadIdx.x;
    const int u  = t & (UNITS - 1);       // output column
    const int h  = t >> 7;                // v-half: 0 -> v[0,64), 1 -> v[64,128)
    const int j0 = blockIdx.x * JB;

    if (t < UNITS) x_sh[t] = x[t];

    // fs tile: 128v x 8j = 1024 floats, 4 per thread.
    #pragma unroll
    for (int k = 0; k < 4; k++) {
        int i = t + k * TPB;
        int v = i >> 3, j = i & (JB - 1);
        int jj = j0 + j;
        fs_sh[v][j] = (jj < WIN - 1) ? state[v * WIN + jj + 1] : x[v];
    }

    // This thread's 64-v slice of w_hi column u: 64 independent LDGs.
    const float* __restrict__ wu = w + h * VH * UNITS + u;  // w_hi[h*64+i][u]
    const float wd = w[2 * UNITS * UNITS + u];              // w_dot[u]
    float wr[VH];
    #pragma unroll
    for (int i = 0; i < VH; i++) wr[i] = wu[i * UNITS];

    __syncthreads();   // fs_sh / x_sh ready

    // q[j] = fs[j].x : 8 warps, warp jw owns one j.
    {
        const int warp = t >> 5, lane = t & 31;
        float p = fs_sh[lane][warp]      * x_sh[lane]
                + fs_sh[lane + 32][warp] * x_sh[lane + 32]
                + fs_sh[lane + 64][warp] * x_sh[lane + 64]
                + fs_sh[lane + 96][warp] * x_sh[lane + 96];
        #pragma unroll
        for (int o = 16; o; o >>= 1) p += __shfl_xor_sync(0xffffffffu, p, o);
        if (lane == 0) q_sh[warp] = p;
    }

    // Partial GEMM over this half's v: {2x LDS.128 + 4x FFMA2} per v.
    u64 s01 = 0, s23 = 0, s45 = 0, s67 = 0;
    #pragma unroll
    for (int i = 0; i < VH; i++) {
        u64 w2 = pack2(wr[i], wr[i]);                 // alu-pipe
        const ulonglong2* fp = (const ulonglong2*)fs_sh[h * VH + i];
        ulonglong2 f = fp[0];                         // j0..3 broadcast
        s01 = ffma2(f.x, w2, s01);
        s23 = ffma2(f.y, w2, s23);
        ulonglong2 g = fp[1];                         // j4..7 broadcast
        s45 = ffma2(g.x, w2, s45);
        s67 = ffma2(g.y, w2, s67);
    }

    float sp[JB];
    unpack2(s01, sp[0], sp[1]);
    unpack2(s23, sp[2], sp[3]);
    unpack2(s45, sp[4], sp[5]);
    unpack2(s67, sp[6], sp[7]);

    // Half-1 publishes its partials (2x STS.128).
    if (h == 1) {
        *(float4*)&comb[u][0] = make_float4(sp[0], sp[1], sp[2], sp[3]);
        *(float4*)&comb[u][4] = make_float4(sp[4], sp[5], sp[6], sp[7]);
    }
    __syncthreads();   // also publishes q_sh

    // Half-0 combines, applies q*wd, and REDG-accumulates (z,c) into g_acc.
    if (h == 0) {
        float z = 0.0f, c = 0.0f;
        #pragma unroll
        for (int j = 0; j < JB; j++) {
            float sj = sp[j] + comb[u][j];
            float e  = __expf(fmaf(q_sh[j], wd, sj));
            z += e;
            c = fmaf(e, fs_sh[u][j], c);              // fs[j][u]
        }
        atomicAdd(&g_acc[u].x, z);                    // RED.ADD (result unused)
        atomicAdd(&g_acc[u].y, c);
    }

    // Ticket: last-arriving block finalizes.
    __threadfence();   // release: REDGs ordered before the ticket
    __syncthreads();
    if (t == 0) s_ticket = atomicAdd(&g_cnt, 1u);
    __syncthreads();

    if (s_ticket == NBLK - 1) {                       // uniform branch (smem bcast)
        __threadfence();   // acquire side
        if (t < UNITS) {
            float2 p = g_acc[t];                      // ONE L2 round
            out[t] = p.y / p.x;
            g_acc[t] = make_float2(0.0f, 0.0f);       // reset for next replay
        }
        if (t == 0) g_cnt = 0;
    }
}

extern "C" void kernel_launch(void* const* d_in, const int* in_sizes, int n_in,
                              void* d_out, int out_size)
{
    const float* x     = (const float*)d_in[0];   // input_tensor (1,128)
    const float* state = (const float*)d_in[1];   // state (128,1024)
    const float* w     = (const float*)d_in[2];   // w (257,128)
    // d_in[3] = b — cancels inside the softmax, unused.

    rsa_fused<<<NBLK, TPB>>>(x, state, w, (float*)d_out);
}

// round 11
// speedup vs baseline: 1.2107x; 1.1840x over previous
#include <cuda_runtime.h>

// RSA_layer: output = c[-1] only  =>  softmax needed only for row i=1023.
//   s[j,u] = (fs @ w_hi)[j,u] + q[j]*w_dot[u],   q[j] = x . fs[j]
//   out[u] = sum_j fs[j,u]*exp(s[j,u]) / sum_j exp(s[j,u])
// Logits O(1) => exp without max-subtraction (validated rel_err ~2e-7).
// fs[j,v] = state[v*1024 + j + 1] for j < 1023;  fs[1023,v] = x[v]
//
// R11: R10 body + scoped-atomic tail (no MEMBAR) + dedicated 129th polling
// block that finalizes the instant the release-counter hits 128.
//  - workers: relaxed REDG partials -> bar.sync -> t0 red.add.release.gpu
//  - poller:  ld.acquire.gpu spin -> one L2 read -> divide -> STG -> reset

#define UNITS 128
#define WIN   1024
#define NBLK  128         // worker blocks; block NBLK is the poller
#define TPB   256
#define JB    8           // j-rows per worker block
#define VH    64          // v-range per half

typedef unsigned long long u64;

__device__ float2 g_acc[UNITS];        // zeroed at load; reset each replay by poller
__device__ unsigned int g_cnt = 0;

__device__ __forceinline__ u64 pack2(float lo, float hi) {
    u64 r;
    asm("mov.b64 %0, {%1, %2};" : "=l"(r) : "f"(lo), "f"(hi));
    return r;
}
__device__ __forceinline__ void unpack2(u64 p, float& lo, float& hi) {
    asm("mov.b64 {%0, %1}, %2;" : "=f"(lo), "=f"(hi) : "l"(p));
}
__device__ __forceinline__ u64 ffma2(u64 a, u64 b, u64 c) {
    u64 d;
    asm("fma.rn.f32x2 %0, %1, %2, %3;" : "=l"(d) : "l"(a), "l"(b), "l"(c));
    return d;
}

__global__ void __launch_bounds__(TPB)
rsa_fused(const float* __restrict__ x,
          const float* __restrict__ state,
          const float* __restrict__ w,
          float* __restrict__ out)
{
    __shared__ __align__(16) float fs_sh[UNITS][JB];   // [v][j], j contiguous (4KB)
    __shared__ float x_sh[UNITS];
    __shared__ float q_sh[JB];
    __shared__ __align__(16) float comb[UNITS][JB];    // half-1 GEMM partials (4KB)

    const int t = threadIdx.x;

    // ---------------- Poller block: spin until all workers released ----------
    if (blockIdx.x == NBLK) {
        __shared__ int s_ready;
        if (t == 0) {
            unsigned int v;
            do {
                asm volatile("ld.acquire.gpu.global.u32 %0, [%1];"
                             : "=r"(v) : "l"(&g_cnt) : "memory");
            } while (v != NBLK);
            s_ready = 1;   // bar below orders everything after the acquire
        }
        __syncthreads();
        if (t < UNITS) {
            float2 p = g_acc[t];                      // one L2 round
            out[t] = p.y / p.x;
            g_acc[t] = make_float2(0.0f, 0.0f);       // reset for next replay
        }
        if (t == 0) g_cnt = 0;
        return;
    }

    // ---------------- Worker blocks -----------------------------------------
    const int u  = t & (UNITS - 1);       // output column
    const int h  = t >> 7;                // v-half: 0 -> v[0,64), 1 -> v[64,128)
    const int j0 = blockIdx.x * JB;

    if (t < UNITS) x_sh[t] = x[t];

    // fs tile: 128v x 8j = 1024 floats, 4 per thread.
    #pragma unroll
    for (int k = 0; k < 4; k++) {
        int i = t + k * TPB;
        int v = i >> 3, j = i & (JB - 1);
        int jj = j0 + j;
        fs_sh[v][j] = (jj < WIN - 1) ? state[v * WIN + jj + 1] : x[v];
    }

    // This thread's 64-v slice of w_hi column u: 64 independent LDGs.
    const float* __restrict__ wu = w + h * VH * UNITS + u;  // w_hi[h*64+i][u]
    const float wd = w[2 * UNITS * UNITS + u];              // w_dot[u]
    float wr[VH];
    #pragma unroll
    for (int i = 0; i < VH; i++) wr[i] = wu[i * UNITS];

    __syncthreads();   // fs_sh / x_sh ready

    // q[j] = fs[j].x : 8 warps, warp jw owns one j.
    {
        const int warp = t >> 5, lane = t & 31;
        float p = fs_sh[lane][warp]      * x_sh[lane]
                + fs_sh[lane + 32][warp] * x_sh[lane + 32]
                + fs_sh[lane + 64][warp] * x_sh[lane + 64]
                + fs_sh[lane + 96][warp] * x_sh[lane + 96];
        #pragma unroll
        for (int o = 16; o; o >>= 1) p += __shfl_xor_sync(0xffffffffu, p, o);
        if (lane == 0) q_sh[warp] = p;
    }

    // Partial GEMM over this half's v: {2x LDS.128 + 4x FFMA2} per v.
    u64 s01 = 0, s23 = 0, s45 = 0, s67 = 0;
    #pragma unroll
    for (int i = 0; i < VH; i++) {
        u64 w2 = pack2(wr[i], wr[i]);                 // alu-pipe
        const ulonglong2* fp = (const ulonglong2*)fs_sh[h * VH + i];
        ulonglong2 f = fp[0];                         // j0..3 broadcast
        s01 = ffma2(f.x, w2, s01);
        s23 = ffma2(f.y, w2, s23);
        ulonglong2 g = fp[1];                         // j4..7 broadcast
        s45 = ffma2(g.x, w2, s45);
        s67 = ffma2(g.y, w2, s67);
    }

    float sp[JB];
    unpack2(s01, sp[0], sp[1]);
    unpack2(s23, sp[2], sp[3]);
    unpack2(s45, sp[4], sp[5]);
    unpack2(s67, sp[6], sp[7]);

    // Half-1 publishes its partials (2x STS.128).
    if (h == 1) {
        *(float4*)&comb[u][0] = make_float4(sp[0], sp[1], sp[2], sp[3]);
        *(float4*)&comb[u][4] = make_float4(sp[4], sp[5], sp[6], sp[7]);
    }
    __syncthreads();   // also publishes q_sh

    // Half-0 combines, applies q*wd, REDG-accumulates (z,c) into g_acc.
    if (h == 0) {
        float z = 0.0f, c = 0.0f;
        #pragma unroll
        for (int j = 0; j < JB; j++) {
            float sj = sp[j] + comb[u][j];
            float e  = __expf(fmaf(q_sh[j], wd, sj));
            z += e;
            c = fmaf(e, fs_sh[u][j], c);              // fs[j][u]
        }
        atomicAdd(&g_acc[u].x, z);                    // relaxed RED.ADD
        atomicAdd(&g_acc[u].y, c);
    }

    // bar.sync + t0 release-add covers the whole block's REDGs (PTX memory
    // model: fence composition through bar). No MEMBAR.
    __syncthreads();
    if (t == 0)
        asm volatile("red.add.release.gpu.global.u32 [%0], %1;"
                     :: "l"(&g_cnt), "r"(1u) : "memory");
}

extern "C" void kernel_launch(void* const* d_in, const int* in_sizes, int n_in,
                              void* d_out, int out_size)
{
    const float* x     = (const float*)d_in[0];   // input_tensor (1,128)
    const float* state = (const float*)d_in[1];   // state (128,1024)
    const float* w     = (const float*)d_in[2];   // w (257,128)
    // d_in[3] = b — cancels inside the softmax, unused.

    rsa_fused<<<NBLK + 1, TPB>>>(x, state, w, (float*)d_out);
}